// round 6
// baseline (speedup 1.0000x reference)
#include <cuda_runtime.h>
#include <cuda_bf16.h>

// Problem shape (fixed by the dataset)
#define BB 32
#define AA 32768
#define CC 21
#define TILE 256
#define NROWBLK (AA / TILE)    // 128 ce blocks per row
#define HB 4096                // 2^12 bins: key bits 31:20
#define NS2 8                  // select blocks per row
#define SEG (AA / NS2)         // 4096 anchors per select segment
#define FULLM 0xFFFFFFFFu

// ---------------- scratch (zero-initialized BSS; left zeroed after each call) --
__device__ float    g_ce[BB * AA];      // per-anchor CE (4 MB)
__device__ float    g_cand[BB * AA];    // boundary-bin compaction buffers
__device__ unsigned g_hist[BB * HB];    // per-row hist of key bits 31:20
__device__ int      g_numpos[BB];
__device__ double   g_locr[BB];
__device__ double   g_pcer[BB];
__device__ double   g_rowsum[BB];       // per-row sum of strictly-above elements
__device__ int      g_arrc[BB];         // ce arrival counter
__device__ int      g_arr2[BB];         // select arrival counter
__device__ unsigned g_ccnt[BB];         // candidate count
__device__ unsigned g_d0[BB], g_krem[BB];
__device__ double   g_fsum;
__device__ int      g_fnp;
__device__ int      g_ticket;

// ---------------- helpers ----------------
__device__ __forceinline__ unsigned tokey(float f) {
    unsigned u = __float_as_uint(f);
    return u ^ ((u & 0x80000000u) ? 0xFFFFFFFFu : 0x80000000u);  // order-preserving
}
__device__ __forceinline__ float fromkey(unsigned k) {
    unsigned u = (k & 0x80000000u) ? (k ^ 0x80000000u) : ~k;
    return __uint_as_float(u);
}

// inclusive suffix scan over the block's threads (NW = warps in block)
template <int NW>
__device__ __forceinline__ unsigned suffix_scan(unsigned v, int tid) {
    __shared__ unsigned s_wt[32];
    const int lane = tid & 31, w = tid >> 5;
    #pragma unroll
    for (int off = 1; off < 32; off <<= 1) {
        unsigned o = __shfl_down_sync(FULLM, v, off);
        if (lane + off < 32) v += o;
    }
    if (lane == 0) s_wt[w] = v;
    __syncthreads();
    if (w == 0) {
        unsigned x = (lane < NW) ? s_wt[lane] : 0u, t2 = x;
        #pragma unroll
        for (int off = 1; off < 32; off <<= 1) {
            unsigned o = __shfl_down_sync(FULLM, t2, off);
            if (lane + off < 32) t2 += o;
        }
        s_wt[lane] = t2 - x;             // strict suffix of warp totals
    }
    __syncthreads();
    v += s_wt[w];
    __syncthreads();
    return v;
}

// ---------------- kernel 1: CE + loc + hist; last row block brackets k --------
__global__ void __launch_bounds__(TILE) ce_kernel(
    const float* __restrict__ loc_p, const float* __restrict__ loc_t,
    const float* __restrict__ cls_p, const int* __restrict__ cls_t)
{
    __shared__ float sh[TILE * CC];
    __shared__ int    s_cnt[8];
    __shared__ double s_loc[8], s_pce[8];
    __shared__ int    s_isl;

    const int b   = blockIdx.y;
    const int a0  = blockIdx.x * TILE;
    const int tid = threadIdx.x;

    {   // coalesced float4 staging of 256x21 logits
        const float4* src = (const float4*)(cls_p + (size_t)(b * AA + a0) * CC);
        float4* dst = (float4*)sh;
        const int n4 = TILE * CC / 4;
        #pragma unroll
        for (int i = tid; i < n4; i += TILE) dst[i] = src[i];
    }
    __syncthreads();

    const int a  = a0 + tid;
    const int ct = cls_t[b * AA + a];
    const float* row = sh + tid * CC;    // stride 21 -> conflict-free

    float mx = row[0];
    #pragma unroll
    for (int c = 1; c < CC; ++c) mx = fmaxf(mx, row[c]);
    float s = 0.f;
    #pragma unroll
    for (int c = 0; c < CC; ++c) s += __expf(row[c] - mx);
    const int tgt = (ct < 0) ? 0 : ct;
    const float ce = mx + __logf(s) - row[tgt];
    g_ce[b * AA + a] = ce;

    {   // warp-aggregated count histogram (key bits 31:20)
        const unsigned dg    = tokey(ce) >> 20;
        const unsigned peers = __match_any_sync(FULLM, dg);
        if ((tid & 31) == (unsigned)(__ffs(peers) - 1))
            atomicAdd(&g_hist[b * HB + dg], (unsigned)__popc(peers));
    }

    const bool pos = (ct > 0);
    float locs = 0.f;
    if (pos) {
        float4 p = ((const float4*)loc_p)[b * AA + a];
        float4 t = ((const float4*)loc_t)[b * AA + a];
        float d;
        d = fabsf(p.x - t.x); locs += (d < 1.f) ? 0.5f * d * d : d - 0.5f;
        d = fabsf(p.y - t.y); locs += (d < 1.f) ? 0.5f * d * d : d - 0.5f;
        d = fabsf(p.z - t.z); locs += (d < 1.f) ? 0.5f * d * d : d - 0.5f;
        d = fabsf(p.w - t.w); locs += (d < 1.f) ? 0.5f * d * d : d - 0.5f;
    }

    int    cnt = pos ? 1 : 0;
    double dl  = (double)locs;
    double dp  = pos ? (double)ce : 0.0;
    #pragma unroll
    for (int o = 16; o; o >>= 1) {
        cnt += __shfl_down_sync(FULLM, cnt, o);
        dl  += __shfl_down_sync(FULLM, dl, o);
        dp  += __shfl_down_sync(FULLM, dp, o);
    }
    const int w = tid >> 5, l = tid & 31;
    if (l == 0) { s_cnt[w] = cnt; s_loc[w] = dl; s_pce[w] = dp; }
    __syncthreads();
    if (w == 0) {
        int    c2 = (l < 8) ? s_cnt[l] : 0;
        double l2 = (l < 8) ? s_loc[l] : 0.0;
        double p2 = (l < 8) ? s_pce[l] : 0.0;
        #pragma unroll
        for (int o = 4; o; o >>= 1) {
            c2 += __shfl_down_sync(FULLM, c2, o);
            l2 += __shfl_down_sync(FULLM, l2, o);
            p2 += __shfl_down_sync(FULLM, p2, o);
        }
        if (l == 0) {
            if (c2)        atomicAdd(&g_numpos[b], c2);
            if (l2 != 0.0) atomicAdd(&g_locr[b], l2);
            if (p2 != 0.0) atomicAdd(&g_pcer[b], p2);
        }
    }

    // ---- last-arriver of this row brackets k in the complete histogram ----
    __threadfence();
    if (tid == 0) s_isl = (atomicAdd(&g_arrc[b], 1) == NROWBLK - 1);
    __syncthreads();
    if (s_isl) {
        __threadfence();                          // acquire siblings' writes
        const int np = g_numpos[b];
        long long kk = 3LL * np; if (kk > AA) kk = AA;
        const unsigned k = (unsigned)kk;
        if (k > 0) {
            unsigned c[16], tot = 0;              // 16 bins/thread (256 thr)
            #pragma unroll
            for (int j = 0; j < 16; ++j) { c[j] = g_hist[b * HB + tid * 16 + j]; tot += c[j]; }
            const unsigned A = suffix_scan<8>(tot, tid);
            unsigned ab = A - tot;                // strictly above my bins
            #pragma unroll
            for (int j = 15; j >= 0; --j) {       // high bin -> low bin
                if (ab < k && k <= ab + c[j]) {
                    g_d0[b] = (unsigned)(tid * 16 + j);
                    g_krem[b] = k - ab;
                }
                ab += c[j];
            }
        }
    }
}

// 1024-thread bracket over 4096 smem bins (4/thread); writes s_dx, s_kx
__device__ __forceinline__ void bracket_smem(const unsigned* s_hist, unsigned kt,
                                             int tid, unsigned* s_dx, unsigned* s_kx)
{
    unsigned c4[4];
    #pragma unroll
    for (int j = 0; j < 4; ++j) c4[j] = s_hist[tid * 4 + j];
    const unsigned tot = c4[0] + c4[1] + c4[2] + c4[3];
    const unsigned A = suffix_scan<32>(tot, tid);
    unsigned ab = A - tot;
    #pragma unroll
    for (int j = 3; j >= 0; --j) {
        if (ab < kt && kt <= ab + c4[j]) { *s_dx = (unsigned)(tid * 4 + j); *s_kx = kt - ab; }
        ab += c4[j];
    }
    __syncthreads();
}

// ---------------- kernel 2: one row pass + last-arriver exact refine ----------
__global__ void __launch_bounds__(1024) select_kernel(float* __restrict__ out)
{
    const int r = blockIdx.y, sp = blockIdx.x, tid = threadIdx.x;
    const unsigned lane = tid & 31;

    __shared__ unsigned s_hist[HB];
    __shared__ unsigned s_dx, s_kx;
    __shared__ double   s_red[32];
    __shared__ int      s_isl;

    const int np = g_numpos[r];
    long long kk = 3LL * np; if (kk > AA) kk = AA;
    const unsigned k = (unsigned)kk;

    unsigned d0 = 0;
    double sumA = 0.0;

    if (k > 0) {
        d0 = g_d0[r];
        // one pass over this block's 4096-anchor segment
        const float4 v = ((const float4*)(g_ce + (size_t)r * AA))[sp * (SEG / 4) + tid];
        const float xs[4] = {v.x, v.y, v.z, v.w};
        #pragma unroll
        for (int e = 0; e < 4; ++e) {
            const float x = xs[e];
            const unsigned dg = tokey(x) >> 20;
            if (dg > d0) sumA += (double)x;
            const bool p = (dg == d0);
            const unsigned m = __ballot_sync(FULLM, p);
            if (m) {
                const int ldr = __ffs(m) - 1;
                unsigned base = 0;
                if ((int)lane == ldr) base = atomicAdd(&g_ccnt[r], (unsigned)__popc(m));
                base = __shfl_sync(FULLM, base, ldr);
                if (p) g_cand[(size_t)r * AA + base + __popc(m & ((1u << lane) - 1u))] = x;
            }
        }
    }
    // block-reduce sumA -> per-row atomic
    #pragma unroll
    for (int o = 16; o; o >>= 1) sumA += __shfl_down_sync(FULLM, sumA, o);
    if (lane == 0) s_red[tid >> 5] = sumA;
    __syncthreads();
    if (tid < 32) {
        double v = s_red[tid];
        #pragma unroll
        for (int o = 16; o; o >>= 1) v += __shfl_down_sync(FULLM, v, o);
        if (tid == 0 && v != 0.0) atomicAdd(&g_rowsum[r], v);
    }
    __syncthreads();

    __threadfence();
    if (tid == 0) s_isl = (atomicAdd(&g_arr2[r], 1) == NS2 - 1);
    __syncthreads();
    if (!s_isl) return;
    __threadfence();                              // acquire siblings' cand writes

    // ---- exact refine over the compacted boundary bin (last block only) ----
    double sum_in = 0.0;
    if (k > 0) {
        const unsigned n    = g_ccnt[r];
        const unsigned krem = g_krem[r];
        const float* cand = g_cand + (size_t)r * AA;

        // pass 1: hist of key bits 19:8
        *(uint4*)(s_hist + tid * 4) = make_uint4(0u, 0u, 0u, 0u);
        __syncthreads();
        for (unsigned i = tid; i < n; i += 1024) {
            const unsigned d = (tokey(cand[i]) >> 8) & 4095u;
            const unsigned act   = __activemask();
            const unsigned peers = __match_any_sync(act, d);
            if (lane == (unsigned)(__ffs(peers) - 1))
                atomicAdd(&s_hist[d], (unsigned)__popc(peers));
        }
        __syncthreads();
        bracket_smem(s_hist, krem, tid, &s_dx, &s_kx);
        const unsigned d1 = s_dx, k2 = s_kx;
        __syncthreads();

        // pass 2: hist of key bits 7:0 within prefix (d0,d1)
        *(uint4*)(s_hist + tid * 4) = make_uint4(0u, 0u, 0u, 0u);
        __syncthreads();
        for (unsigned i = tid; i < n; i += 1024) {
            const unsigned key = tokey(cand[i]);
            if (((key >> 8) & 4095u) == d1) {
                const unsigned d = key & 255u;
                const unsigned act   = __activemask();
                const unsigned peers = __match_any_sync(act, d);
                if (lane == (unsigned)(__ffs(peers) - 1))
                    atomicAdd(&s_hist[d], (unsigned)__popc(peers));
            }
        }
        __syncthreads();
        bracket_smem(s_hist, k2, tid, &s_dx, &s_kx);   // bins >255 are zero
        const unsigned T  = (d0 << 20) | (d1 << 8) | s_dx;
        const unsigned k3 = s_kx;
        __syncthreads();

        // pass 3: exact sum of cand elements strictly above T, + k3 ties at T
        double acc = (tid == 0) ? (double)k3 * (double)fromkey(T) : 0.0;
        for (unsigned i = tid; i < n; i += 1024) {
            const float x = cand[i];
            if (tokey(x) > T) acc += (double)x;
        }
        #pragma unroll
        for (int o = 16; o; o >>= 1) acc += __shfl_down_sync(FULLM, acc, o);
        if (lane == 0) s_red[tid >> 5] = acc;
        __syncthreads();
        if (tid < 32) {
            double v = s_red[tid];
            #pragma unroll
            for (int o = 16; o; o >>= 1) v += __shfl_down_sync(FULLM, v, o);
            if (tid == 0) sum_in = v;
        }
    }

    // reset this row's histogram for the next replay (all 1024 threads)
    *(uint4*)(g_hist + r * HB + tid * 4) = make_uint4(0u, 0u, 0u, 0u);

    if (tid == 0) {
        const double rowtot = sum_in + g_rowsum[r] + g_locr[r] + g_pcer[r];
        atomicAdd(&g_fsum, rowtot);
        atomicAdd(&g_fnp, np);
        g_rowsum[r] = 0.0; g_locr[r] = 0.0; g_pcer[r] = 0.0;
        g_numpos[r] = 0;   g_ccnt[r] = 0u;
        g_arrc[r] = 0;     g_arr2[r] = 0;
        g_d0[r] = 0u;      g_krem[r] = 0u;
        __threadfence();
        const int tk = atomicAdd(&g_ticket, 1);
        if (tk == BB - 1) {              // global last finisher
            const double fs = atomicAdd(&g_fsum, 0.0);
            const int    fn = atomicAdd(&g_fnp, 0);
            out[0] = (float)(fs / (double)fn);
            g_fsum = 0.0; g_fnp = 0; g_ticket = 0;
            __threadfence();
        }
    }
}

// ---------------- launch (2 kernels) ----------------
extern "C" void kernel_launch(void* const* d_in, const int* in_sizes, int n_in,
                              void* d_out, int out_size)
{
    const float* loc_p = (const float*)d_in[0];
    const float* loc_t = (const float*)d_in[1];
    const float* cls_p = (const float*)d_in[2];
    const int*   cls_t = (const int*)d_in[3];

    dim3 grid1(NROWBLK, BB);
    ce_kernel<<<grid1, TILE>>>(loc_p, loc_t, cls_p, cls_t);
    dim3 grid2(NS2, BB);
    select_kernel<<<grid2, 1024>>>((float*)d_out);
}

// round 7
// speedup vs baseline: 1.7590x; 1.7590x over previous
#include <cuda_runtime.h>
#include <cuda_bf16.h>

// Problem shape (fixed by the dataset)
#define BB 32
#define AA 32768
#define CC 21
#define TILE 256
#define HB 4096                // 2^12 bins: key bits 31:20 (and refine bits 19:8)
#define NS2 8                  // select blocks per row
#define SEG (AA / NS2)         // 4096 anchors per select segment
#define FULLM 0xFFFFFFFFu

// ---------------- scratch (zero-initialized BSS; left zeroed after each call) --
__device__ float    g_ce[BB * AA];      // per-anchor CE (4 MB, L2-resident)
__device__ unsigned g_hist[BB * HB];    // per-row hist of key bits 31:20
__device__ unsigned g_h2c[BB * HB];     // refine count hist (bits 19:8 of d0 bin)
__device__ float    g_h2s[BB * HB];     // refine value-sum hist
__device__ int      g_numpos[BB];
__device__ double   g_locr[BB];
__device__ double   g_pcer[BB];
__device__ double   g_rowsum[BB];       // per-row strictly-above sum
__device__ int      g_arr2[BB];         // select arrival counter
__device__ double   g_fsum;
__device__ int      g_fnp;
__device__ int      g_ticket;

// ---------------- helpers ----------------
__device__ __forceinline__ unsigned tokey(float f) {
    unsigned u = __float_as_uint(f);
    return u ^ ((u & 0x80000000u) ? 0xFFFFFFFFu : 0x80000000u);  // order-preserving
}
__device__ __forceinline__ float fromkey(unsigned k) {
    unsigned u = (k & 0x80000000u) ? (k ^ 0x80000000u) : ~k;
    return __uint_as_float(u);
}

// inclusive suffix scan over 1024 block threads
__device__ __forceinline__ unsigned suffix_scan(unsigned v, int tid) {
    __shared__ unsigned s_wt[32];
    const int lane = tid & 31, w = tid >> 5;
    #pragma unroll
    for (int off = 1; off < 32; off <<= 1) {
        unsigned o = __shfl_down_sync(FULLM, v, off);
        if (lane + off < 32) v += o;
    }
    if (lane == 0) s_wt[w] = v;
    __syncthreads();
    if (w == 0) {
        unsigned x = s_wt[lane], t2 = x;
        #pragma unroll
        for (int off = 1; off < 32; off <<= 1) {
            unsigned o = __shfl_down_sync(FULLM, t2, off);
            if (lane + off < 32) t2 += o;
        }
        s_wt[lane] = t2 - x;             // strict suffix of warp totals
    }
    __syncthreads();
    v += s_wt[w];
    __syncthreads();
    return v;
}

// block-wide double sum (valid in tid 0)
__device__ __forceinline__ double dsum_block(double v, int tid, double* s_red) {
    const int lane = tid & 31;
    #pragma unroll
    for (int o = 16; o; o >>= 1) v += __shfl_down_sync(FULLM, v, o);
    if (lane == 0) s_red[tid >> 5] = v;
    __syncthreads();
    double r = 0.0;
    if (tid < 32) {
        double x = s_red[tid];
        #pragma unroll
        for (int o = 16; o; o >>= 1) x += __shfl_down_sync(FULLM, x, o);
        r = x;
    }
    __syncthreads();
    return r;
}

// ---------------- kernel 1: CE + loc loss + per-row count histogram ------------
// (identical to the proven 23.6us version: no fences, no tail work)
__global__ void __launch_bounds__(TILE) ce_kernel(
    const float* __restrict__ loc_p, const float* __restrict__ loc_t,
    const float* __restrict__ cls_p, const int* __restrict__ cls_t)
{
    __shared__ float sh[TILE * CC];
    __shared__ int    s_cnt[8];
    __shared__ double s_loc[8], s_pce[8];

    const int b   = blockIdx.y;
    const int a0  = blockIdx.x * TILE;
    const int tid = threadIdx.x;

    {   // coalesced float4 staging of 256x21 logits
        const float4* src = (const float4*)(cls_p + (size_t)(b * AA + a0) * CC);
        float4* dst = (float4*)sh;
        const int n4 = TILE * CC / 4;
        #pragma unroll
        for (int i = tid; i < n4; i += TILE) dst[i] = src[i];
    }
    __syncthreads();

    const int a  = a0 + tid;
    const int ct = cls_t[b * AA + a];
    const float* row = sh + tid * CC;    // stride 21 -> conflict-free

    float mx = row[0];
    #pragma unroll
    for (int c = 1; c < CC; ++c) mx = fmaxf(mx, row[c]);
    float s = 0.f;
    #pragma unroll
    for (int c = 0; c < CC; ++c) s += __expf(row[c] - mx);
    const int tgt = (ct < 0) ? 0 : ct;
    const float ce = mx + __logf(s) - row[tgt];
    g_ce[b * AA + a] = ce;

    {   // warp-aggregated count histogram (key bits 31:20)
        const unsigned dg    = tokey(ce) >> 20;
        const unsigned peers = __match_any_sync(FULLM, dg);
        if ((tid & 31) == (unsigned)(__ffs(peers) - 1))
            atomicAdd(&g_hist[b * HB + dg], (unsigned)__popc(peers));
    }

    const bool pos = (ct > 0);
    float locs = 0.f;
    if (pos) {
        float4 p = ((const float4*)loc_p)[b * AA + a];
        float4 t = ((const float4*)loc_t)[b * AA + a];
        float d;
        d = fabsf(p.x - t.x); locs += (d < 1.f) ? 0.5f * d * d : d - 0.5f;
        d = fabsf(p.y - t.y); locs += (d < 1.f) ? 0.5f * d * d : d - 0.5f;
        d = fabsf(p.z - t.z); locs += (d < 1.f) ? 0.5f * d * d : d - 0.5f;
        d = fabsf(p.w - t.w); locs += (d < 1.f) ? 0.5f * d * d : d - 0.5f;
    }

    int    cnt = pos ? 1 : 0;
    double dl  = (double)locs;
    double dp  = pos ? (double)ce : 0.0;
    #pragma unroll
    for (int o = 16; o; o >>= 1) {
        cnt += __shfl_down_sync(FULLM, cnt, o);
        dl  += __shfl_down_sync(FULLM, dl, o);
        dp  += __shfl_down_sync(FULLM, dp, o);
    }
    const int w = tid >> 5, l = tid & 31;
    if (l == 0) { s_cnt[w] = cnt; s_loc[w] = dl; s_pce[w] = dp; }
    __syncthreads();
    if (w == 0) {
        int    c2 = (l < 8) ? s_cnt[l] : 0;
        double l2 = (l < 8) ? s_loc[l] : 0.0;
        double p2 = (l < 8) ? s_pce[l] : 0.0;
        #pragma unroll
        for (int o = 4; o; o >>= 1) {
            c2 += __shfl_down_sync(FULLM, c2, o);
            l2 += __shfl_down_sync(FULLM, l2, o);
            p2 += __shfl_down_sync(FULLM, p2, o);
        }
        if (l == 0) {
            if (c2)        atomicAdd(&g_numpos[b], c2);
            if (l2 != 0.0) atomicAdd(&g_locr[b], l2);
            if (p2 != 0.0) atomicAdd(&g_pcer[b], p2);
        }
    }
}

// ---------------- kernel 2: 8 blocks/row, one data pass, last-arriver refine ---
__global__ void __launch_bounds__(1024) select_kernel(float* __restrict__ out)
{
    const int r = blockIdx.y, sp = blockIdx.x, tid = threadIdx.x;

    __shared__ unsigned s_c[HB];        // refine count hist (16 KB)
    __shared__ float    s_s[HB];        // refine sum hist   (16 KB)
    __shared__ unsigned s_d0, s_kr, s_cb, s_d1, s_k2;
    __shared__ double   s_red[32];
    __shared__ int      s_isl;

    const int np = g_numpos[r];
    long long kk = 3LL * np; if (kk > AA) kk = AA;
    const unsigned k = (unsigned)kk;
    const int hbase = r * HB + tid * 4;

    double sumA = 0.0;

    if (k > 0) {
        // ---- bracket k in the complete 12-bit histogram (every block; no wait)
        {
            const uint4 cv = *(const uint4*)(g_hist + hbase);
            const unsigned c4[4] = {cv.x, cv.y, cv.z, cv.w};
            const unsigned tot = c4[0] + c4[1] + c4[2] + c4[3];
            const unsigned A = suffix_scan(tot, tid);
            unsigned ab = A - tot;               // strictly above my 4 bins
            #pragma unroll
            for (int j = 3; j >= 0; --j) {       // high bin -> low bin
                if (ab < k && k <= ab + c4[j]) {
                    s_d0 = (unsigned)(tid * 4 + j); s_kr = k - ab; s_cb = c4[j];
                }
                ab += c4[j];
            }
        }
        __syncthreads();
        const unsigned d0 = s_d0;

        // ---- one pass over this block's segment ----
        *(uint4*)(s_c + tid * 4)   = make_uint4(0u, 0u, 0u, 0u);
        *(float4*)(s_s + tid * 4)  = make_float4(0.f, 0.f, 0.f, 0.f);
        __syncthreads();
        {
            const float4 v = ((const float4*)(g_ce + (size_t)r * AA))[sp * (SEG / 4) + tid];
            const float xs[4] = {v.x, v.y, v.z, v.w};
            #pragma unroll
            for (int e = 0; e < 4; ++e) {
                const float x = xs[e];
                const unsigned key = tokey(x);
                const unsigned dg  = key >> 20;
                if (dg > d0) sumA += (double)x;
                else if (dg == d0) {             // rare (~3%): smem hist, bits 19:8
                    const unsigned d1 = (key >> 8) & 4095u;
                    atomicAdd(&s_c[d1], 1u);
                    atomicAdd(&s_s[d1], x);
                }
            }
        }
        __syncthreads();
        // sparse flush of the refine histogram (fire-and-forget REDs)
        #pragma unroll
        for (int j = 0; j < 4; ++j) {
            const unsigned c = s_c[tid * 4 + j];
            if (c) {
                atomicAdd(&g_h2c[hbase + j], c);
                atomicAdd(&g_h2s[hbase + j], s_s[tid * 4 + j]);
            }
        }
    }

    // block-reduce sumA -> per-row double RED
    {
        const double t = dsum_block(sumA, tid, s_red);
        if (tid == 0 && t != 0.0) atomicAdd(&g_rowsum[r], t);
    }

    // arrival (only REDs in flight -> fence is cheap)
    __threadfence();
    if (tid == 0) s_isl = (atomicAdd(&g_arr2[r], 1) == NS2 - 1);
    __syncthreads();
    if (!s_isl) return;
    __threadfence();                     // acquire siblings' REDs

    // ---- last-arriver per row: refine from histograms (no data pass) ----
    double refine = 0.0;
    if (k > 0) {
        const unsigned krem = s_kr, cbin = s_cb, d0 = s_d0;
        unsigned c4[4]; float v4[4];
        #pragma unroll
        for (int j = 0; j < 4; ++j) {
            c4[j] = g_h2c[hbase + j];
            v4[j] = g_h2s[hbase + j];
        }
        if (krem == cbin) {              // whole boundary bin: exact
            double la = (double)v4[0] + (double)v4[1] + (double)v4[2] + (double)v4[3];
            refine = dsum_block(la, tid, s_red);
        } else {
            const unsigned tot = c4[0] + c4[1] + c4[2] + c4[3];
            const unsigned A = suffix_scan(tot, tid);
            unsigned ab = A - tot;
            #pragma unroll
            for (int j = 3; j >= 0; --j) {
                if (ab < krem && krem <= ab + c4[j]) {
                    s_d1 = (unsigned)(tid * 4 + j); s_k2 = krem - ab;
                }
                ab += c4[j];
            }
            __syncthreads();
            const unsigned d1 = s_d1, k2 = s_k2;
            double la = 0.0;
            #pragma unroll
            for (int j = 0; j < 4; ++j)
                if ((unsigned)(tid * 4 + j) > d1) la += (double)v4[j];
            refine = dsum_block(la, tid, s_red);
            if (tid == 0)                // ties at 24-bit base: rel err <= 2^-15
                refine += (double)k2 * (double)fromkey((d0 << 20) | (d1 << 8));
        }
    }

    // reset this row's histograms for the next graph replay
    *(uint4*)(g_hist + hbase) = make_uint4(0u, 0u, 0u, 0u);
    *(uint4*)(g_h2c + hbase)  = make_uint4(0u, 0u, 0u, 0u);
    *(float4*)(g_h2s + hbase) = make_float4(0.f, 0.f, 0.f, 0.f);

    if (tid == 0) {
        const double rowtot = refine + g_rowsum[r] + g_locr[r] + g_pcer[r];
        atomicAdd(&g_fsum, rowtot);
        atomicAdd(&g_fnp, np);
        g_rowsum[r] = 0.0; g_locr[r] = 0.0; g_pcer[r] = 0.0;
        g_numpos[r] = 0;   g_arr2[r] = 0;
        __threadfence();
        const int tk = atomicAdd(&g_ticket, 1);
        if (tk == BB - 1) {              // global last finisher
            const double fs = atomicAdd(&g_fsum, 0.0);
            const int    fn = atomicAdd(&g_fnp, 0);
            out[0] = (float)(fs / (double)fn);
            g_fsum = 0.0; g_fnp = 0; g_ticket = 0;
            __threadfence();
        }
    }
}

// ---------------- launch (2 kernels) ----------------
extern "C" void kernel_launch(void* const* d_in, const int* in_sizes, int n_in,
                              void* d_out, int out_size)
{
    const float* loc_p = (const float*)d_in[0];
    const float* loc_t = (const float*)d_in[1];
    const float* cls_p = (const float*)d_in[2];
    const int*   cls_t = (const int*)d_in[3];

    dim3 grid1(AA / TILE, BB);
    ce_kernel<<<grid1, TILE>>>(loc_p, loc_t, cls_p, cls_t);
    dim3 grid2(NS2, BB);
    select_kernel<<<grid2, 1024>>>((float*)d_out);
}